// round 4
// baseline (speedup 1.0000x reference)
#include <cuda_runtime.h>

#define NF 8
#define NK 16
#define BB 32
#define YY 32
#define XX 32
#define PP 16
#define TT 8

__device__ float g_ky[NF*NK*YY];
__device__ float g_kx[NF*NK*XX];
__device__ float g_kp[NF*NK*PP];
__device__ float g_kt[NF*NK*TT];
__device__ float4 g_qmean4[YY*XX*PP*TT/4];
__device__ float g_integral[NF*NK];

// ---- packed f32x2 helpers (Blackwell FFMA2) ----
__device__ __forceinline__ float2 ffma2(float2 a, float2 b, float2 c) {
    float2 d;
    asm("{\n\t"
        ".reg .b64 ra, rb, rc, rd;\n\t"
        "mov.b64 ra, {%2, %3};\n\t"
        "mov.b64 rb, {%4, %5};\n\t"
        "mov.b64 rc, {%6, %7};\n\t"
        "fma.rn.f32x2 rd, ra, rb, rc;\n\t"
        "mov.b64 {%0, %1}, rd;\n\t"
        "}"
        : "=f"(d.x), "=f"(d.y)
        : "f"(a.x), "f"(a.y), "f"(b.x), "f"(b.y), "f"(c.x), "f"(c.y));
    return d;
}
__device__ __forceinline__ float2 fmul2(float2 a, float2 b) {
    float2 d;
    asm("{\n\t"
        ".reg .b64 ra, rb, rd;\n\t"
        "mov.b64 ra, {%2, %3};\n\t"
        "mov.b64 rb, {%4, %5};\n\t"
        "mul.rn.f32x2 rd, ra, rb;\n\t"
        "mov.b64 {%0, %1}, rd;\n\t"
        "}"
        : "=f"(d.x), "=f"(d.y)
        : "f"(a.x), "f"(a.y), "f"(b.x), "f"(b.y));
    return d;
}

// ---- Kernel 1: qmean over batch (float4, high MLP) + block-0 tables/zeroing ----
__global__ __launch_bounds__(128)
void prep_kernel(const float* __restrict__ quad,
                 const float* __restrict__ mean_lat, const float* __restrict__ logstd_lat,
                 const float* __restrict__ mean_lon, const float* __restrict__ logstd_lon,
                 const float* __restrict__ mean_lev, const float* __restrict__ logstd_lev,
                 const float* __restrict__ logtau,   float* __restrict__ out) {
    const int tid = threadIdx.x;
    const int i = blockIdx.x * 128 + tid;          // 256 blocks * 128 = 32768 float4s
    const float4* q4 = reinterpret_cast<const float4*>(quad);
    float sx = 0.0f, sy = 0.0f, sz = 0.0f, sw = 0.0f;
    #pragma unroll 8
    for (int b = 0; b < BB; ++b) {
        float4 v = q4[(size_t)b * 32768 + i];
        sx += v.x; sy += v.y; sz += v.z; sw += v.w;
    }
    const float inv = 1.0f / (float)BB;
    g_qmean4[i] = make_float4(sx * inv, sy * inv, sz * inv, sw * inv);

    if (blockIdx.x == 0) {
        // tid in [0,128) = (f,k)
        {
            float m = mean_lat[tid], inv_s = 1.0f / expf(logstd_lat[tid]);
            #pragma unroll
            for (int k = 0; k < YY; ++k) {
                float c = -1.0f + 2.0f * (float)k / (float)(YY - 1);
                float z = (c - m) * inv_s;
                g_ky[tid * YY + k] = expf(-0.5f * z * z);
            }
        }
        {
            float m = mean_lon[tid], inv_s = 1.0f / expf(logstd_lon[tid]);
            #pragma unroll
            for (int k = 0; k < XX; ++k) {
                float c = -1.0f + 2.0f * (float)k / (float)(XX - 1);
                float z = (c - m) * inv_s;
                g_kx[tid * XX + k] = expf(-0.5f * z * z);
            }
        }
        {
            float m = mean_lev[tid], inv_s = 1.0f / expf(logstd_lev[tid]);
            #pragma unroll
            for (int k = 0; k < PP; ++k) {
                float c = -1.0f + 2.0f * (float)k / (float)(PP - 1);
                float z = (c - m) * inv_s;
                g_kp[tid * PP + k] = expf(-0.5f * z * z);
            }
        }
        {
            float inv_tau = 1.0f / (expf(logtau[tid]) + 1e-4f);
            #pragma unroll
            for (int t = 0; t < TT; ++t)
                g_kt[tid * TT + t] = expf(-(float)t * inv_tau);
        }
        g_integral[tid] = 0.0f;
        #pragma unroll
        for (int j = 0; j < BB; ++j)
            out[tid * BB + j] = 0.0f;
    }
}

// ---- Kernel 2: main fused pass + integral side-job ----
// grid = 1024 = (b:32) x (ychunk:16, 2 y each) x (fhalf:2)
// 256 threads = 8 warps = (f_local:4) x (k-half:2). Lane owns (p, t-quad).
// Block bx also computes integral partial for cell (y,x) = (bx>>5, bx&31).
__global__ __launch_bounds__(256, 3)
void feat_kernel(const float* __restrict__ field, const float* __restrict__ quad,
                 float* __restrict__ out) {
    __shared__ float4 sq4[1024];             // 16KB quad row
    __shared__ float2 s_cf[4 * 8 * 32];      // 8KB: ky*kx per (f_local, k-pair, x)
    __shared__ float  s_iq[128];             // integral side-job qmean cell

    const int tid  = threadIdx.x;
    const int lane = tid & 31;
    const int wid  = tid >> 5;
    const int f_local = wid >> 1;
    const int kh   = wid & 1;
    const int bx   = blockIdx.x;
    const int b    = bx >> 5;
    const int ych  = (bx >> 1) & 15;
    const int fh   = bx & 1;
    const int f    = fh * 4 + f_local;
    const int p    = lane >> 1;
    const int t0   = (lane & 1) * 4;

    // integral side-job, part 1: stage this block's (y,x) cell of qmean
    if (tid < 32) {
        float4 v = g_qmean4[bx * 32 + tid];
        reinterpret_cast<float4*>(s_iq)[tid] = v;
    }

    // per-lane packed weights for this warp's 4 k-pairs
    float2 w2[4][4];
    #pragma unroll
    for (int m = 0; m < 4; ++m) {
        int k0 = 2 * (kh * 4 + m);
        float kp0 = g_kp[(f * NK + k0) * PP + p];
        float kp1 = g_kp[(f * NK + k0 + 1) * PP + p];
        #pragma unroll
        for (int j = 0; j < 4; ++j) {
            w2[m][j].x = kp0 * g_kt[(f * NK + k0) * TT + t0 + j];
            w2[m][j].y = kp1 * g_kt[(f * NK + k0 + 1) * TT + t0 + j];
        }
    }
    __syncthreads();

    // integral side-job, part 2: separable contraction for this block's cell
    if (tid < 128) {
        const float* kt = &g_kt[tid * TT];
        const float* kp = &g_kp[tid * PP];
        float s = 0.0f;
        #pragma unroll
        for (int pp = 0; pp < PP; ++pp) {
            float st = 0.0f;
            #pragma unroll
            for (int t = 0; t < TT; ++t)
                st += kt[t] * s_iq[pp * TT + t];
            s += kp[pp] * st;
        }
        int yc = bx >> 5, xc = bx & 31;
        atomicAdd(&g_integral[tid], s * g_ky[tid * YY + yc] * g_kx[tid * XX + xc]);
    }

    float2 acc[4];
    #pragma unroll
    for (int m = 0; m < 4; ++m) acc[m] = make_float2(0.0f, 0.0f);

    for (int yy = 0; yy < 2; ++yy) {
        int y = ych * 2 + yy;
        __syncthreads();
        // stage quad row (16KB), coalesced
        const float4* qrow = reinterpret_cast<const float4*>(quad + (size_t)(b * YY + y) * 4096);
        #pragma unroll
        for (int i = 0; i < 4; ++i)
            sq4[tid + 256 * i] = qrow[tid + 256 * i];
        // build ky*kx table: 1024 float2, 4 per thread
        #pragma unroll
        for (int e = 0; e < 4; ++e) {
            int idx = tid * 4 + e;
            int fl = idx >> 8;
            int kp_i = (idx >> 5) & 7;
            int x = idx & 31;
            int fg = fh * 4 + fl;
            int k0 = 2 * kp_i;
            s_cf[idx] = make_float2(
                g_ky[(fg * NK + k0) * YY + y] * g_kx[(fg * NK + k0) * XX + x],
                g_ky[(fg * NK + k0 + 1) * YY + y] * g_kx[(fg * NK + k0 + 1) * XX + x]);
        }
        __syncthreads();

        const float4* frow = reinterpret_cast<const float4*>(
            field + (size_t)((b * NF + f) * YY + y) * 4096);
        const float2* cf = &s_cf[(f_local * 8 + kh * 4) * 32];

        #pragma unroll 8
        for (int x = 0; x < XX; ++x) {
            float4 fv = frow[x * 32 + lane];   // contiguous 512B per warp-instr
            float4 qv = sq4[x * 32 + lane];    // conflict-free LDS.128
            float g0 = fv.x * qv.x;
            float g1 = fv.y * qv.y;
            float g2 = fv.z * qv.z;
            float g3 = fv.w * qv.w;
            float2 gg0 = make_float2(g0, g0);
            float2 gg1 = make_float2(g1, g1);
            float2 gg2 = make_float2(g2, g2);
            float2 gg3 = make_float2(g3, g3);
            #pragma unroll
            for (int m = 0; m < 4; ++m) {
                float2 s = fmul2(gg0, w2[m][0]);
                s = ffma2(gg1, w2[m][1], s);
                s = ffma2(gg2, w2[m][2], s);
                s = ffma2(gg3, w2[m][3], s);
                acc[m] = ffma2(s, cf[m * 32 + x], acc[m]);
            }
        }
    }

    // warp reduction over lanes (= over p,t), one atomic per k
    #pragma unroll
    for (int m = 0; m < 4; ++m) {
        float sx = acc[m].x, sy = acc[m].y;
        #pragma unroll
        for (int off = 16; off > 0; off >>= 1) {
            sx += __shfl_down_sync(0xffffffffu, sx, off);
            sy += __shfl_down_sync(0xffffffffu, sy, off);
        }
        if (lane == 0) {
            int kbase = b * (NF * NK) + f * NK + kh * 8 + 2 * m;
            atomicAdd(&out[kbase],     sx);
            atomicAdd(&out[kbase + 1], sy);
        }
    }
}

// ---- Kernel 3: normalize by integral ----
__global__ void norm_kernel(float* __restrict__ out) {
    int i = blockIdx.x * 256 + threadIdx.x;   // 4096
    out[i] = out[i] / (g_integral[i & 127] + 1e-4f);
}

extern "C" void kernel_launch(void* const* d_in, const int* in_sizes, int n_in,
                              void* d_out, int out_size) {
    const float* field      = (const float*)d_in[0];
    const float* quad       = (const float*)d_in[1];
    const float* mean_lat   = (const float*)d_in[2];
    const float* logstd_lat = (const float*)d_in[3];
    const float* mean_lon   = (const float*)d_in[4];
    const float* logstd_lon = (const float*)d_in[5];
    const float* mean_lev   = (const float*)d_in[6];
    const float* logstd_lev = (const float*)d_in[7];
    const float* logtau     = (const float*)d_in[8];
    float* out = (float*)d_out;

    prep_kernel<<<256, 128>>>(quad, mean_lat, logstd_lat, mean_lon, logstd_lon,
                              mean_lev, logstd_lev, logtau, out);
    feat_kernel<<<1024, 256>>>(field, quad, out);
    norm_kernel<<<16, 256>>>(out);
}

// round 5
// speedup vs baseline: 1.3788x; 1.3788x over previous
#include <cuda_runtime.h>

#define NF 8
#define NK 16
#define BB 32
#define YY 32
#define XX 32
#define PP 16
#define TT 8

__device__ float g_ky[NF*NK*YY];
__device__ float g_kx[NF*NK*XX];
__device__ float g_kp[NF*NK*PP];
__device__ float g_kt[NF*NK*TT];
__device__ float4 g_qmean4[YY*XX*PP*TT/4];
__device__ float g_integral[NF*NK];

// ---- packed f32x2 helpers (Blackwell FFMA2) ----
__device__ __forceinline__ float2 ffma2(float2 a, float2 b, float2 c) {
    float2 d;
    asm("{\n\t"
        ".reg .b64 ra, rb, rc, rd;\n\t"
        "mov.b64 ra, {%2, %3};\n\t"
        "mov.b64 rb, {%4, %5};\n\t"
        "mov.b64 rc, {%6, %7};\n\t"
        "fma.rn.f32x2 rd, ra, rb, rc;\n\t"
        "mov.b64 {%0, %1}, rd;\n\t"
        "}"
        : "=f"(d.x), "=f"(d.y)
        : "f"(a.x), "f"(a.y), "f"(b.x), "f"(b.y), "f"(c.x), "f"(c.y));
    return d;
}
__device__ __forceinline__ float2 fmul2(float2 a, float2 b) {
    float2 d;
    asm("{\n\t"
        ".reg .b64 ra, rb, rd;\n\t"
        "mov.b64 ra, {%2, %3};\n\t"
        "mov.b64 rb, {%4, %5};\n\t"
        "mul.rn.f32x2 rd, ra, rb;\n\t"
        "mov.b64 {%0, %1}, rd;\n\t"
        "}"
        : "=f"(d.x), "=f"(d.y)
        : "f"(a.x), "f"(a.y), "f"(b.x), "f"(b.y));
    return d;
}

// ---- Kernel 1: qmean (batch split 4-way across threads) + block-0 tables ----
// 512 blocks x 256 threads. Block handles 64 float4 elements; thread group
// g = tid>>6 sums batches [8g, 8g+8). All loads coalesced (512B/warp), MLP=8.
__global__ __launch_bounds__(256)
void prep_kernel(const float* __restrict__ quad,
                 const float* __restrict__ mean_lat, const float* __restrict__ logstd_lat,
                 const float* __restrict__ mean_lon, const float* __restrict__ logstd_lon,
                 const float* __restrict__ mean_lev, const float* __restrict__ logstd_lev,
                 const float* __restrict__ logtau,   float* __restrict__ out) {
    __shared__ float4 sdata[256];
    const int tid = threadIdx.x;
    const int el  = (tid & 63);
    const int g   = tid >> 6;                       // 0..3
    const int e   = blockIdx.x * 64 + el;           // 512*64 = 32768 float4s
    const float4* q4 = reinterpret_cast<const float4*>(quad);

    float sx = 0.0f, sy = 0.0f, sz = 0.0f, sw = 0.0f;
    #pragma unroll
    for (int bb = 0; bb < 8; ++bb) {
        float4 v = q4[(size_t)(g * 8 + bb) * 32768 + e];
        sx += v.x; sy += v.y; sz += v.z; sw += v.w;
    }
    sdata[tid] = make_float4(sx, sy, sz, sw);
    __syncthreads();
    if (g == 0) {
        float4 a = sdata[tid + 64];
        float4 c = sdata[tid + 128];
        float4 d = sdata[tid + 192];
        const float inv = 1.0f / (float)BB;
        g_qmean4[e] = make_float4((sx + a.x + c.x + d.x) * inv,
                                  (sy + a.y + c.y + d.y) * inv,
                                  (sz + a.z + c.z + d.z) * inv,
                                  (sw + a.w + c.w + d.w) * inv);
    }

    if (blockIdx.x == 0) {
        if (tid < 128) {
            {
                float m = mean_lat[tid], inv_s = 1.0f / expf(logstd_lat[tid]);
                #pragma unroll
                for (int k = 0; k < YY; ++k) {
                    float c = -1.0f + 2.0f * (float)k / (float)(YY - 1);
                    float z = (c - m) * inv_s;
                    g_ky[tid * YY + k] = expf(-0.5f * z * z);
                }
            }
            {
                float m = mean_lon[tid], inv_s = 1.0f / expf(logstd_lon[tid]);
                #pragma unroll
                for (int k = 0; k < XX; ++k) {
                    float c = -1.0f + 2.0f * (float)k / (float)(XX - 1);
                    float z = (c - m) * inv_s;
                    g_kx[tid * XX + k] = expf(-0.5f * z * z);
                }
            }
            {
                float m = mean_lev[tid], inv_s = 1.0f / expf(logstd_lev[tid]);
                #pragma unroll
                for (int k = 0; k < PP; ++k) {
                    float c = -1.0f + 2.0f * (float)k / (float)(PP - 1);
                    float z = (c - m) * inv_s;
                    g_kp[tid * PP + k] = expf(-0.5f * z * z);
                }
            }
            {
                float inv_tau = 1.0f / (expf(logtau[tid]) + 1e-4f);
                #pragma unroll
                for (int t = 0; t < TT; ++t)
                    g_kt[tid * TT + t] = expf(-(float)t * inv_tau);
            }
            g_integral[tid] = 0.0f;
        }
        #pragma unroll
        for (int j = tid; j < NF*NK*BB; j += 256)
            out[j] = 0.0f;
    }
}

// ---- Kernel 2: main fused pass + integral side-job ----
// grid = 1024 = (b:32) x (ychunk:16, 2 y each) x (fhalf:2)
// 256 threads = 8 warps = (f_local:4) x (k-half:2). Lane owns (p, t-quad).
// Block bx also computes integral partial for cell (y,x) = (bx>>5, bx&31).
__global__ __launch_bounds__(256, 2)
void feat_kernel(const float* __restrict__ field, const float* __restrict__ quad,
                 float* __restrict__ out) {
    __shared__ float4 sq4[1024];             // 16KB quad row
    __shared__ float2 s_cf[4 * 8 * 32];      // 8KB: ky*kx per (f_local, k-pair, x)
    __shared__ float  s_iq[128];             // integral side-job qmean cell

    const int tid  = threadIdx.x;
    const int lane = tid & 31;
    const int wid  = tid >> 5;
    const int f_local = wid >> 1;
    const int kh   = wid & 1;
    const int bx   = blockIdx.x;
    const int b    = bx >> 5;
    const int ych  = (bx >> 1) & 15;
    const int fh   = bx & 1;
    const int f    = fh * 4 + f_local;
    const int p    = lane >> 1;
    const int t0   = (lane & 1) * 4;

    // integral side-job, part 1: stage this block's (y,x) cell of qmean
    if (tid < 32) {
        float4 v = g_qmean4[bx * 32 + tid];
        reinterpret_cast<float4*>(s_iq)[tid] = v;
    }

    // per-lane packed weights for this warp's 4 k-pairs
    float2 w2[4][4];
    #pragma unroll
    for (int m = 0; m < 4; ++m) {
        int k0 = 2 * (kh * 4 + m);
        float kp0 = g_kp[(f * NK + k0) * PP + p];
        float kp1 = g_kp[(f * NK + k0 + 1) * PP + p];
        #pragma unroll
        for (int j = 0; j < 4; ++j) {
            w2[m][j].x = kp0 * g_kt[(f * NK + k0) * TT + t0 + j];
            w2[m][j].y = kp1 * g_kt[(f * NK + k0 + 1) * TT + t0 + j];
        }
    }
    __syncthreads();

    // integral side-job, part 2: separable contraction for this block's cell
    if (tid < 128) {
        const float* kt = &g_kt[tid * TT];
        const float* kp = &g_kp[tid * PP];
        float s = 0.0f;
        #pragma unroll
        for (int pp = 0; pp < PP; ++pp) {
            float st = 0.0f;
            #pragma unroll
            for (int t = 0; t < TT; ++t)
                st += kt[t] * s_iq[pp * TT + t];
            s += kp[pp] * st;
        }
        int yc = bx >> 5, xc = bx & 31;
        atomicAdd(&g_integral[tid], s * g_ky[tid * YY + yc] * g_kx[tid * XX + xc]);
    }

    float2 acc[4];
    #pragma unroll
    for (int m = 0; m < 4; ++m) acc[m] = make_float2(0.0f, 0.0f);

    for (int yy = 0; yy < 2; ++yy) {
        int y = ych * 2 + yy;
        __syncthreads();
        // stage quad row (16KB), coalesced
        const float4* qrow = reinterpret_cast<const float4*>(quad + (size_t)(b * YY + y) * 4096);
        #pragma unroll
        for (int i = 0; i < 4; ++i)
            sq4[tid + 256 * i] = qrow[tid + 256 * i];
        // build ky*kx table: 1024 float2, 4 per thread
        #pragma unroll
        for (int e = 0; e < 4; ++e) {
            int idx = tid * 4 + e;
            int fl = idx >> 8;
            int kp_i = (idx >> 5) & 7;
            int x = idx & 31;
            int fg = fh * 4 + fl;
            int k0 = 2 * kp_i;
            s_cf[idx] = make_float2(
                g_ky[(fg * NK + k0) * YY + y] * g_kx[(fg * NK + k0) * XX + x],
                g_ky[(fg * NK + k0 + 1) * YY + y] * g_kx[(fg * NK + k0 + 1) * XX + x]);
        }
        __syncthreads();

        const float4* frow = reinterpret_cast<const float4*>(
            field + (size_t)((b * NF + f) * YY + y) * 4096);
        const float2* cf = &s_cf[(f_local * 8 + kh * 4) * 32];

        #pragma unroll 8
        for (int x = 0; x < XX; ++x) {
            float4 fv = frow[x * 32 + lane];   // contiguous 512B per warp-instr
            float4 qv = sq4[x * 32 + lane];    // conflict-free LDS.128
            float g0 = fv.x * qv.x;
            float g1 = fv.y * qv.y;
            float g2 = fv.z * qv.z;
            float g3 = fv.w * qv.w;
            float2 gg0 = make_float2(g0, g0);
            float2 gg1 = make_float2(g1, g1);
            float2 gg2 = make_float2(g2, g2);
            float2 gg3 = make_float2(g3, g3);
            #pragma unroll
            for (int m = 0; m < 4; ++m) {
                float2 s = fmul2(gg0, w2[m][0]);
                s = ffma2(gg1, w2[m][1], s);
                s = ffma2(gg2, w2[m][2], s);
                s = ffma2(gg3, w2[m][3], s);
                acc[m] = ffma2(s, cf[m * 32 + x], acc[m]);
            }
        }
    }

    // warp reduction over lanes (= over p,t), one atomic per k
    #pragma unroll
    for (int m = 0; m < 4; ++m) {
        float sx = acc[m].x, sy = acc[m].y;
        #pragma unroll
        for (int off = 16; off > 0; off >>= 1) {
            sx += __shfl_down_sync(0xffffffffu, sx, off);
            sy += __shfl_down_sync(0xffffffffu, sy, off);
        }
        if (lane == 0) {
            int kbase = b * (NF * NK) + f * NK + kh * 8 + 2 * m;
            atomicAdd(&out[kbase],     sx);
            atomicAdd(&out[kbase + 1], sy);
        }
    }
}

// ---- Kernel 3: normalize by integral ----
__global__ void norm_kernel(float* __restrict__ out) {
    int i = blockIdx.x * 256 + threadIdx.x;   // 4096
    out[i] = out[i] / (g_integral[i & 127] + 1e-4f);
}

extern "C" void kernel_launch(void* const* d_in, const int* in_sizes, int n_in,
                              void* d_out, int out_size) {
    const float* field      = (const float*)d_in[0];
    const float* quad       = (const float*)d_in[1];
    const float* mean_lat   = (const float*)d_in[2];
    const float* logstd_lat = (const float*)d_in[3];
    const float* mean_lon   = (const float*)d_in[4];
    const float* logstd_lon = (const float*)d_in[5];
    const float* mean_lev   = (const float*)d_in[6];
    const float* logstd_lev = (const float*)d_in[7];
    const float* logtau     = (const float*)d_in[8];
    float* out = (float*)d_out;

    prep_kernel<<<512, 256>>>(quad, mean_lat, logstd_lat, mean_lon, logstd_lon,
                              mean_lev, logstd_lev, logtau, out);
    feat_kernel<<<1024, 256>>>(field, quad, out);
    norm_kernel<<<16, 256>>>(out);
}